// round 14
// baseline (speedup 1.0000x reference)
#include <cuda_runtime.h>
#include <cuda_bf16.h>
#include <math.h>
#include <stdint.h>

#define BDIM 4
#define CDIM 256
#define NDIM 4096
#define MBOUND 64.0f

// ---------------- global scratch (static device allocations) ---------------
__device__ __nv_bfloat16 g_Qh[(size_t)BDIM * NDIM * CDIM];  // (B,N,C)
__device__ __nv_bfloat16 g_Ql[(size_t)BDIM * NDIM * CDIM];
__device__ __nv_bfloat16 g_Kh[(size_t)BDIM * NDIM * CDIM];  // (B,N,C)
__device__ __nv_bfloat16 g_Kl[(size_t)BDIM * NDIM * CDIM];
__device__ __nv_bfloat16 g_Vh[(size_t)BDIM * CDIM * NDIM];  // (B,C,N)
__device__ __nv_bfloat16 g_Vl[(size_t)BDIM * CDIM * NDIM];
__device__ __nv_bfloat16 g_Ph[(size_t)BDIM * NDIM * NDIM];  // exp(S-64) hi
__device__ __nv_bfloat16 g_Pl[(size_t)BDIM * NDIM * NDIM];  // exp(S-64) lo
__device__ float g_part[(size_t)BDIM * NDIM * 32];          // per-(row, mtile) sums
__device__ float g_linv[(size_t)BDIM * NDIM];               // 1/rowsum

// ---------------- PTX helpers (baseline sm_80+ features only) ---------------
__device__ __forceinline__ uint32_t smem_u32(const void* p) {
    uint32_t a;
    asm("{ .reg .u64 t; cvta.to.shared.u64 t, %1; cvt.u32.u64 %0, t; }"
        : "=r"(a) : "l"(p));
    return a;
}
__device__ __forceinline__ void ldsm4(uint32_t* r, uint32_t addr) {
    asm volatile("ldmatrix.sync.aligned.m8n8.x4.shared.b16 {%0,%1,%2,%3}, [%4];"
                 : "=r"(r[0]), "=r"(r[1]), "=r"(r[2]), "=r"(r[3]) : "r"(addr));
}
// NOTE: non-volatile on purpose — pure register op; lets ptxas schedule/
// interleave MMAs instead of preserving source-order dependency chains.
__device__ __forceinline__ void mma_bf16(float* d, const uint32_t* a,
                                         const uint32_t* b) {
    asm("mma.sync.aligned.m16n8k16.row.col.f32.bf16.bf16.f32 "
        "{%0,%1,%2,%3}, {%4,%5,%6,%7}, {%8,%9}, {%0,%1,%2,%3};"
        : "+f"(d[0]), "+f"(d[1]), "+f"(d[2]), "+f"(d[3])
        : "r"(a[0]), "r"(a[1]), "r"(a[2]), "r"(a[3]), "r"(b[0]), "r"(b[1]));
}
__device__ __forceinline__ void cp16(uint32_t daddr, const void* src) {
    asm volatile("cp.async.ca.shared.global [%0], [%1], 16;"
                 :: "r"(daddr), "l"(src));
}
#define CP_COMMIT() asm volatile("cp.async.commit_group;" ::: "memory")
#define CP_WAIT1()  asm volatile("cp.async.wait_group 1;" ::: "memory")
#define CP_WAIT0()  asm volatile("cp.async.wait_group 0;" ::: "memory")

// ---------------------------------------------------------------------------
// Split-bf16 warp-MMA GEMM mainloop, v5 (R10 geometry + term-major order).
//   acc(128x128 fp32) = sum_k A[128,K] * B[128,K]^T, 3-term hi/lo split:
//   acc += Ah*Bh + Ah*Bl + Al*Bh  (Al*Bl dropped, ~2^-18 error).
// K chunks of 32, 2-stage cp.async double buffer. 80B padded rows
// (conflict-free ldmatrix). 8 warps = 4(m) x 2(n); warp tile 32x64.
// SMEM rows/stage: [0,128) Ah [128,256) Al [256,384) Bh [384,512) Bl.
// ---------------------------------------------------------------------------
#define SROW      80
#define BUF_BYTES (512 * SROW)          // 40960
#define GEMM_SMEM (2 * BUF_BYTES)       // 81920

__device__ __forceinline__ void gemm_mainloop(
    const __nv_bfloat16* __restrict__ Ah, const __nv_bfloat16* __restrict__ Al,
    const __nv_bfloat16* __restrict__ Bh, const __nv_bfloat16* __restrict__ Bl,
    int kstride, int nchunks, float acc[2][8][4])
{
    extern __shared__ __align__(16) char smem[];
    const uint32_t sb = smem_u32(smem);
    const int tid  = threadIdx.x;
    const int lane = tid & 31;
    const int wid  = tid >> 5;
    const int m0   = (wid & 3) * 32;
    const int n0w  = (wid >> 2) * 64;

    // ---- staging map: 8 x 16B cp.async per thread per chunk ---------------
    const __nv_bfloat16* src[8];
    uint32_t dof[8];
    #pragma unroll
    for (int i = 0; i < 8; i++) {
        int u = i * 256 + tid;
        int row = u >> 2, c16 = u & 3;
        const __nv_bfloat16* base;
        int r;
        if (row < 128)      { base = Ah; r = row; }
        else if (row < 256) { base = Al; r = row - 128; }
        else if (row < 384) { base = Bh; r = row - 256; }
        else                { base = Bl; r = row - 384; }
        src[i] = base + (size_t)r * kstride + c16 * 8;
        dof[i] = sb + (uint32_t)row * SROW + c16 * 16;
    }

    // ---- ldmatrix lane addressing -----------------------------------------
    const int g = lane >> 3, r8 = lane & 7;
    const int rowA = (g & 1) * 8 + r8, kkA = (g >> 1) * 8;  // a frag order
    const int rowB = (g >> 1) * 8 + r8, kkB = (g & 1) * 8;  // b pairs
    uint32_t aAh[2], aAl[2], aBh[4], aBl[4];
    #pragma unroll
    for (int mt = 0; mt < 2; mt++) {
        aAh[mt] = sb + (uint32_t)(0   + m0 + mt * 16 + rowA) * SROW + kkA * 2;
        aAl[mt] = sb + (uint32_t)(128 + m0 + mt * 16 + rowA) * SROW + kkA * 2;
    }
    #pragma unroll
    for (int np = 0; np < 4; np++) {
        aBh[np] = sb + (uint32_t)(256 + n0w + np * 16 + rowB) * SROW + kkB * 2;
        aBl[np] = sb + (uint32_t)(384 + n0w + np * 16 + rowB) * SROW + kkB * 2;
    }

    #pragma unroll
    for (int mt = 0; mt < 2; mt++)
        #pragma unroll
        for (int nt = 0; nt < 8; nt++)
            #pragma unroll
            for (int e = 0; e < 4; e++) acc[mt][nt][e] = 0.f;

    // prologue: stage chunk 0 into buffer 0
    #pragma unroll
    for (int i = 0; i < 8; i++) cp16(dof[i], src[i]);
    CP_COMMIT();

    for (int ci = 0; ci < nchunks; ci++) {
        const uint32_t bofs = (ci & 1) ? BUF_BYTES : 0;
        if (ci + 1 < nchunks) {
            const uint32_t nofs = (ci & 1) ? 0 : BUF_BYTES;
            const int co = (ci + 1) * 32;
            #pragma unroll
            for (int i = 0; i < 8; i++) cp16(dof[i] + nofs, src[i] + co);
            CP_COMMIT();
            CP_WAIT1();
        } else {
            CP_WAIT0();
        }
        __syncthreads();

        #pragma unroll
        for (int k16 = 0; k16 < 2; k16++) {
            const uint32_t kb = bofs + k16 * 32;
            uint32_t ah[2][4], al[2][4], bh[4][4], bl[4][4];
            #pragma unroll
            for (int mt = 0; mt < 2; mt++) {
                ldsm4(ah[mt], aAh[mt] + kb);
                ldsm4(al[mt], aAl[mt] + kb);
            }
            #pragma unroll
            for (int np = 0; np < 4; np++) {
                ldsm4(bh[np], aBh[np] + kb);
                ldsm4(bl[np], aBl[np] + kb);
            }
            // term-major: same-acc MMAs are 16 apart -> no RAW chains
            #pragma unroll
            for (int mt = 0; mt < 2; mt++)
                #pragma unroll
                for (int nt = 0; nt < 8; nt++)
                    mma_bf16(acc[mt][nt], ah[mt], &bh[nt >> 1][(nt & 1) * 2]);
            #pragma unroll
            for (int mt = 0; mt < 2; mt++)
                #pragma unroll
                for (int nt = 0; nt < 8; nt++)
                    mma_bf16(acc[mt][nt], ah[mt], &bl[nt >> 1][(nt & 1) * 2]);
            #pragma unroll
            for (int mt = 0; mt < 2; mt++)
                #pragma unroll
                for (int nt = 0; nt < 8; nt++)
                    mma_bf16(acc[mt][nt], al[mt], &bh[nt >> 1][(nt & 1) * 2]);
        }
        __syncthreads();   // compute done before this buffer is restaged
    }
}

// ---------------------------------------------------------------------------
// QK + exp(S-64): writes unnormalized P (bf16 hi/lo, exact truncation split)
// and per-(row, mtile) partial sums.  Tile: 128 n-rows x 128 m-cols.
// ---------------------------------------------------------------------------
__global__ __launch_bounds__(256, 1) void qk_kernel()
{
    const int mtile = blockIdx.x;   // key tile (128 wide)
    const int ntile = blockIdx.y;   // query tile (128 tall)
    const int b     = blockIdx.z;
    const size_t ao = ((size_t)b * NDIM + (size_t)ntile * 128) * CDIM;
    const size_t bo = ((size_t)b * NDIM + (size_t)mtile * 128) * CDIM;

    float acc[2][8][4];
    gemm_mainloop(g_Qh + ao, g_Ql + ao, g_Kh + bo, g_Kl + bo,
                  CDIM, CDIM / 32, acc);

    extern __shared__ __align__(16) char smem[];
    const int tid = threadIdx.x, lane = tid & 31, wid = tid >> 5;
    const int m0 = (wid & 3) * 32, n0w = (wid >> 2) * 64;
    const int er = lane >> 2, ec = (lane & 3) * 2;

    float rs[4] = {0.f, 0.f, 0.f, 0.f};   // rows m0 + mt*16 + er (+8)
    #pragma unroll
    for (int mt = 0; mt < 2; mt++)
        #pragma unroll
        for (int nt = 0; nt < 8; nt++) {
            float e0 = __expf(acc[mt][nt][0] - MBOUND);
            float e1 = __expf(acc[mt][nt][1] - MBOUND);
            float e2 = __expf(acc[mt][nt][2] - MBOUND);
            float e3 = __expf(acc[mt][nt][3] - MBOUND);
            rs[mt * 2 + 0] += e0 + e1;
            rs[mt * 2 + 1] += e2 + e3;

            // exact truncation split: hi = trunc16(e); lo = e - hi (bf16-exact)
            uint32_t u0 = __float_as_uint(e0), u1 = __float_as_uint(e1);
            uint32_t u2 = __float_as_uint(e2), u3 = __float_as_uint(e3);
            float l0 = e0 - __uint_as_float(u0 & 0xffff0000u);
            float l1 = e1 - __uint_as_float(u1 & 0xffff0000u);
            float l2 = e2 - __uint_as_float(u2 & 0xffff0000u);
            float l3 = e3 - __uint_as_float(u3 & 0xffff0000u);
            uint32_t ph01 = __byte_perm(u0, u1, 0x7632);
            uint32_t ph23 = __byte_perm(u2, u3, 0x7632);
            uint32_t pl01 = __byte_perm(__float_as_uint(l0), __float_as_uint(l1), 0x7632);
            uint32_t pl23 = __byte_perm(__float_as_uint(l2), __float_as_uint(l3), 0x7632);

            const int nrow = ntile * 128 + m0 + mt * 16 + er;
            const int mcol = mtile * 128 + n0w + nt * 8 + ec;
            const size_t o0 = ((size_t)b * NDIM + nrow) * NDIM + mcol;
            const size_t o1 = ((size_t)b * NDIM + nrow + 8) * NDIM + mcol;
            *(uint32_t*)&g_Ph[o0] = ph01;
            *(uint32_t*)&g_Pl[o0] = pl01;
            *(uint32_t*)&g_Ph[o1] = ph23;
            *(uint32_t*)&g_Pl[o1] = pl23;
        }

    // reduce over the 4 lanes sharing a row, then over the 2 n-half warps
    #pragma unroll
    for (int r = 0; r < 4; r++) {
        rs[r] += __shfl_xor_sync(0xffffffffu, rs[r], 1);
        rs[r] += __shfl_xor_sync(0xffffffffu, rs[r], 2);
    }
    __syncthreads();                     // mainloop smem free for reuse
    float* part = (float*)smem;          // [128 rows][2 n-halves]
    if ((lane & 3) == 0) {
        #pragma unroll
        for (int r = 0; r < 4; r++) {
            const int row = m0 + (r >> 1) * 16 + (r & 1) * 8 + er;
            part[row * 2 + (wid >> 2)] = rs[r];
        }
    }
    __syncthreads();
    if (tid < 128) {
        const float s = part[tid * 2] + part[tid * 2 + 1];
        g_part[((size_t)b * NDIM + ntile * 128 + tid) * 32 + mtile] = s;
    }
}

// ---------------------------------------------------------------------------
// Row-sum reduce: linv[b][n] = 1 / sum_mtile part[b][n][mtile]
// ---------------------------------------------------------------------------
__global__ __launch_bounds__(256) void reduce_kernel()
{
    const int idx = blockIdx.x * 256 + threadIdx.x;   // b*NDIM + n
    const float4* p = (const float4*)&g_part[(size_t)idx * 32];
    float s = 0.f;
    #pragma unroll
    for (int i = 0; i < 8; i++) {
        float4 v = p[i];
        s += (v.x + v.y) + (v.z + v.w);
    }
    g_linv[idx] = 1.f / s;
}

// ---------------------------------------------------------------------------
// PV: out[b,c,n] = linv[n] * sum_m V[c,m] * P[n,m].  A=V rows c, B=P rows n.
// ---------------------------------------------------------------------------
__global__ __launch_bounds__(256, 1) void pv_kernel(float* __restrict__ out)
{
    const int ntile = blockIdx.x;   // n tile (128 wide)
    const int ct    = blockIdx.y;   // channel tile (128 tall)
    const int b     = blockIdx.z;
    const size_t ao = ((size_t)b * CDIM + (size_t)ct * 128) * NDIM;
    const size_t bo = ((size_t)b * NDIM + (size_t)ntile * 128) * NDIM;

    float acc[2][8][4];
    gemm_mainloop(g_Vh + ao, g_Vl + ao, g_Ph + bo, g_Pl + bo,
                  NDIM, NDIM / 32, acc);

    const int tid = threadIdx.x, lane = tid & 31, wid = tid >> 5;
    const int m0 = (wid & 3) * 32, n0w = (wid >> 2) * 64;
    const int er = lane >> 2, ec = (lane & 3) * 2;

    #pragma unroll
    for (int nt = 0; nt < 8; nt++) {
        const int cc = ntile * 128 + n0w + nt * 8 + ec;
        const float i0 = g_linv[(size_t)b * NDIM + cc];
        const float i1 = g_linv[(size_t)b * NDIM + cc + 1];
        #pragma unroll
        for (int mt = 0; mt < 2; mt++) {
            const int rr = ct * 128 + m0 + mt * 16 + er;
            *(float2*)&out[((size_t)b * CDIM + rr) * NDIM + cc] =
                make_float2(acc[mt][nt][0] * i0, acc[mt][nt][1] * i1);
            *(float2*)&out[((size_t)b * CDIM + rr + 8) * NDIM + cc] =
                make_float2(acc[mt][nt][2] * i0, acc[mt][nt][3] * i1);
        }
    }
}

// ---------------------------------------------------------------------------
// Projection: out = W(256x256) @ X(256x4096) + bias; emits bf16 hi/lo splits.
// Q,K stored (B,N,C); V stored (B,C,N).
// ---------------------------------------------------------------------------
union BF4 { __nv_bfloat16 h[4]; uint2 u; };

__global__ __launch_bounds__(256) void proj_kernel(
    const float* __restrict__ x,
    const float* __restrict__ Wq, const float* __restrict__ bq,
    const float* __restrict__ Wk, const float* __restrict__ bk,
    const float* __restrict__ Wv, const float* __restrict__ bv)
{
    __shared__ float w_s[16][68];
    __shared__ float x_s[16][64];

    const int n0 = blockIdx.x * 64;
    const int o0 = blockIdx.y * 64;
    const int b     = blockIdx.z / 3;
    const int which = blockIdx.z % 3;
    const float* W    = (which == 0) ? Wq : (which == 1) ? Wk : Wv;
    const float* bias = (which == 0) ? bq : (which == 1) ? bk : bv;

    const int t  = threadIdx.x;
    const int tx = t & 15;
    const int ty = t >> 4;

    const float* xb = x + (size_t)b * CDIM * NDIM;

    float acc[4][4];
    #pragma unroll
    for (int i = 0; i < 4; i++)
        #pragma unroll
        for (int j = 0; j < 4; j++) acc[i][j] = 0.f;

    const int lo = t >> 2;
    const int lc = (t & 3) << 2;
    const int xr = t >> 4;
    const int xn = (t & 15) << 2;

    for (int c0 = 0; c0 < CDIM; c0 += 16) {
        float4 wv4 = *(const float4*)&W[(size_t)(o0 + lo) * CDIM + c0 + lc];
        float4 xv4 = *(const float4*)&xb[(size_t)(c0 + xr) * NDIM + n0 + xn];
        __syncthreads();
        w_s[lc + 0][lo] = wv4.x;
        w_s[lc + 1][lo] = wv4.y;
        w_s[lc + 2][lo] = wv4.z;
        w_s[lc + 3][lo] = wv4.w;
        *(float4*)&x_s[xr][xn] = xv4;
        __syncthreads();
        #pragma unroll
        for (int kk = 0; kk < 16; kk++) {
            float4 a4 = *(const float4*)&w_s[kk][ty << 2];
            float4 b4 = *(const float4*)&x_s[kk][tx << 2];
            float a[4] = {a4.x, a4.y, a4.z, a4.w};
            float bb[4] = {b4.x, b4.y, b4.z, b4.w};
            #pragma unroll
            for (int i = 0; i < 4; i++)
                #pragma unroll
                for (int j = 0; j < 4; j++)
                    acc[i][j] = fmaf(a[i], bb[j], acc[i][j]);
        }
    }

    float bo[4];
    #pragma unroll
    for (int i = 0; i < 4; i++) bo[i] = bias[o0 + (ty << 2) + i];

    if (which != 2) {
        __nv_bfloat16* dh = (which == 0) ? g_Qh : g_Kh;
        __nv_bfloat16* dl = (which == 0) ? g_Ql : g_Kl;
        #pragma unroll
        for (int j = 0; j < 4; j++) {
            const int n = n0 + (tx << 2) + j;
            BF4 H, L;
            #pragma unroll
            for (int i = 0; i < 4; i++) {
                float v = acc[i][j] + bo[i];
                H.h[i] = __float2bfloat16(v);
                L.h[i] = __float2bfloat16(v - __bfloat162float(H.h[i]));
            }
            const size_t base = ((size_t)b * NDIM + n) * CDIM + o0 + (ty << 2);
            *(uint2*)&dh[base] = H.u;
            *(uint2*)&dl[base] = L.u;
        }
    } else {
        #pragma unroll
        for (int i = 0; i < 4; i++) {
            const int o = o0 + (ty << 2) + i;
            BF4 H, L;
            #pragma unroll
            for (int j = 0; j < 4; j++) {
                float v = acc[i][j] + bo[i];
                H.h[j] = __float2bfloat16(v);
                L.h[j] = __float2bfloat16(v - __bfloat162float(H.h[j]));
            }
            const size_t base = ((size_t)b * CDIM + o) * NDIM + n0 + (tx << 2);
            *(uint2*)&g_Vh[base] = H.u;
            *(uint2*)&g_Vl[base] = L.u;
        }
    }
}

// ---------------------------------------------------------------------------
extern "C" void kernel_launch(void* const* d_in, const int* in_sizes, int n_in,
                              void* d_out, int out_size)
{
    const float* x  = (const float*)d_in[0];
    const float* Wq = (const float*)d_in[1];
    const float* bq = (const float*)d_in[2];
    const float* Wk = (const float*)d_in[3];
    const float* bk = (const float*)d_in[4];
    const float* Wv = (const float*)d_in[5];
    const float* bv = (const float*)d_in[6];
    float* out = (float*)d_out;

    cudaFuncSetAttribute(qk_kernel,
                         cudaFuncAttributeMaxDynamicSharedMemorySize, GEMM_SMEM);
    cudaFuncSetAttribute(pv_kernel,
                         cudaFuncAttributeMaxDynamicSharedMemorySize, GEMM_SMEM);

    dim3 pg(NDIM / 64, CDIM / 64, BDIM * 3);
    proj_kernel<<<pg, 256>>>(x, Wq, bq, Wk, bk, Wv, bv);

    dim3 qg(NDIM / 128, NDIM / 128, BDIM);       // (mtiles, ntiles, B)
    qk_kernel<<<qg, 256, GEMM_SMEM>>>();

    reduce_kernel<<<(BDIM * NDIM) / 256, 256>>>();

    dim3 vg(NDIM / 128, CDIM / 128, BDIM);       // (ntiles, ctiles, B)
    pv_kernel<<<vg, 256, GEMM_SMEM>>>(out);
}

// round 15
// speedup vs baseline: 1.0351x; 1.0351x over previous
#include <cuda_runtime.h>
#include <cuda_bf16.h>
#include <math.h>
#include <stdint.h>

#define BDIM 4
#define CDIM 256
#define NDIM 4096
#define MBOUND 64.0f

// ---------------- global scratch (static device allocations) ---------------
__device__ __nv_bfloat16 g_Qh[(size_t)BDIM * NDIM * CDIM];  // (B,N,C)
__device__ __nv_bfloat16 g_Ql[(size_t)BDIM * NDIM * CDIM];
__device__ __nv_bfloat16 g_Kh[(size_t)BDIM * NDIM * CDIM];  // (B,N,C)
__device__ __nv_bfloat16 g_Kl[(size_t)BDIM * NDIM * CDIM];
__device__ __nv_bfloat16 g_Vh[(size_t)BDIM * CDIM * NDIM];  // (B,C,N)
__device__ __nv_bfloat16 g_Vl[(size_t)BDIM * CDIM * NDIM];
__device__ __nv_bfloat16 g_Ph[(size_t)BDIM * NDIM * NDIM];  // exp(S-64) hi
__device__ __nv_bfloat16 g_Pl[(size_t)BDIM * NDIM * NDIM];  // exp(S-64) lo
__device__ float g_part[(size_t)BDIM * NDIM * 32];          // per-(row, mtile) sums
__device__ float g_linv[(size_t)BDIM * NDIM];               // 1/rowsum

// ---------------- PTX helpers (baseline sm_80+ features only) ---------------
__device__ __forceinline__ uint32_t smem_u32(const void* p) {
    uint32_t a;
    asm("{ .reg .u64 t; cvta.to.shared.u64 t, %1; cvt.u32.u64 %0, t; }"
        : "=r"(a) : "l"(p));
    return a;
}
__device__ __forceinline__ void ldsm4(uint32_t* r, uint32_t addr) {
    asm volatile("ldmatrix.sync.aligned.m8n8.x4.shared.b16 {%0,%1,%2,%3}, [%4];"
                 : "=r"(r[0]), "=r"(r[1]), "=r"(r[2]), "=r"(r[3]) : "r"(addr));
}
// non-volatile on purpose: pure register op, lets ptxas schedule freely
__device__ __forceinline__ void mma_bf16(float* d, const uint32_t* a,
                                         const uint32_t* b) {
    asm("mma.sync.aligned.m16n8k16.row.col.f32.bf16.bf16.f32 "
        "{%0,%1,%2,%3}, {%4,%5,%6,%7}, {%8,%9}, {%0,%1,%2,%3};"
        : "+f"(d[0]), "+f"(d[1]), "+f"(d[2]), "+f"(d[3])
        : "r"(a[0]), "r"(a[1]), "r"(a[2]), "r"(a[3]), "r"(b[0]), "r"(b[1]));
}
__device__ __forceinline__ void cp16(uint32_t daddr, const void* src) {
    asm volatile("cp.async.ca.shared.global [%0], [%1], 16;"
                 :: "r"(daddr), "l"(src));
}
#define CP_COMMIT() asm volatile("cp.async.commit_group;" ::: "memory")
#define CP_WAIT1()  asm volatile("cp.async.wait_group 1;" ::: "memory")
#define CP_WAIT0()  asm volatile("cp.async.wait_group 0;" ::: "memory")

// ===========================================================================
// QK kernel v6: Q-persistent SMEM + continuous K ring across 4 mtiles.
//   S(128n x 128m per mtile) = Q[128,256] * K[128,256]^T, 3-term bf16 split.
//   CTA = (ntile, 4 consecutive mtiles). 32 k-chunks stream through a
//   3-stage cp.async ring with NO drain at mtile boundaries; epilogue
//   (exp(S-64), truncation split, P store, partial row sums) overlaps the
//   next mtile's staging.  8 warps = 4(m=n-rows) x 2(n=m-cols), warp 32x64.
// SMEM: Q [256 rows(hi128+lo128) x 528B] = 132 KB (bank-distinct: 132 % 32
//       words = 4 -> 8-row ldmatrix groups hit distinct banks)
//       K ring: 3 stages x [256 rows(hi128+lo128) x 80B] = 60 KB
//       part scratch: 1 KB
// ===========================================================================
#define QROW      528
#define QSMEM_B   (256 * QROW)            // 135168
#define KROW      80
#define KSTAGE_B  (256 * KROW)            // 20480
#define QK_SMEM   (QSMEM_B + 3 * KSTAGE_B + 1024)   // 197632

__global__ __launch_bounds__(256, 1) void qk_kernel()
{
    extern __shared__ __align__(16) char smem[];
    const uint32_t sbq = smem_u32(smem);
    const uint32_t sbk = sbq + QSMEM_B;
    float* part = (float*)(smem + QSMEM_B + 3 * KSTAGE_B);

    const int tid  = threadIdx.x;
    const int lane = tid & 31;
    const int wid  = tid >> 5;
    const int mg    = blockIdx.x;    // mtile group (4 mtiles each)
    const int ntile = blockIdx.y;
    const int b     = blockIdx.z;
    const int m0  = (wid & 3) * 32;   // S-tile row block (query rows)
    const int n0w = (wid >> 2) * 64;  // S-tile col block (key cols)

    // ---- stage Q (persistent): 256 rows x 32 x 16B units, one group ------
    #pragma unroll
    for (int i = 0; i < 32; i++) {
        const int id  = i * 256 + tid;
        const int row = id >> 5, c16 = id & 31;
        const __nv_bfloat16* src = (row < 128 ? g_Qh : g_Ql)
            + ((size_t)b * NDIM + ntile * 128 + (row & 127)) * CDIM + c16 * 8;
        cp16(sbq + row * QROW + c16 * 16, src);
    }
    CP_COMMIT();

    // ---- K staging map: 4 x 16B per thread per chunk ----------------------
    const __nv_bfloat16* ksrc[4];
    uint32_t kdof[4];
    #pragma unroll
    for (int j = 0; j < 4; j++) {
        const int id  = j * 256 + tid;
        const int row = id >> 2, c16 = id & 3;
        ksrc[j] = (row < 128 ? g_Kh : g_Kl)
            + ((size_t)b * NDIM + (size_t)mg * 512 + (row & 127)) * CDIM + c16 * 8;
        kdof[j] = sbk + row * KROW + c16 * 16;
    }
    // issue chunk ci into stage (ci % 3); chunk = (mtile_local<<3) | k-chunk
    #define ISSUE_K(ci) do {                                                   \
        const int _c = (ci);                                                   \
        const size_t _ko = (size_t)(_c >> 3) * (128 * CDIM) + (_c & 7) * 32;   \
        const uint32_t _so = (uint32_t)(_c % 3) * KSTAGE_B;                    \
        _Pragma("unroll")                                                      \
        for (int j = 0; j < 4; j++) cp16(kdof[j] + _so, ksrc[j] + _ko);        \
        CP_COMMIT();                                                           \
    } while (0)

    // ---- ldmatrix lane addressing -----------------------------------------
    const int g = lane >> 3, r8 = lane & 7;
    const int rowA = (g & 1) * 8 + r8, kkA = (g >> 1) * 8;
    const int rowB = (g >> 1) * 8 + r8, kkB = (g & 1) * 8;
    uint32_t aQ[2], aK[4];
    #pragma unroll
    for (int mt = 0; mt < 2; mt++)
        aQ[mt] = sbq + (uint32_t)(m0 + mt * 16 + rowA) * QROW + kkA * 2;
    #pragma unroll
    for (int np = 0; np < 4; np++)
        aK[np] = sbk + (uint32_t)(n0w + np * 16 + rowB) * KROW + kkB * 2;

    float acc[2][8][4];
    #pragma unroll
    for (int mt = 0; mt < 2; mt++)
        #pragma unroll
        for (int nt = 0; nt < 8; nt++)
            #pragma unroll
            for (int e = 0; e < 4; e++) acc[mt][nt][e] = 0.f;

    // prologue: K chunks 0, 1
    ISSUE_K(0);
    ISSUE_K(1);

    const int er = lane >> 2, ec = (lane & 3) * 2;

    for (int ci = 0; ci < 32; ci++) {
        if (ci < 31) CP_WAIT1(); else CP_WAIT0();   // chunk ci resident
        __syncthreads();
        if (ci + 2 < 32) ISSUE_K(ci + 2);           // into buf freed by ci-1

        const uint32_t sofs = (uint32_t)(ci % 3) * KSTAGE_B;
        const uint32_t qofs = (uint32_t)(ci & 7) * 64;
        #pragma unroll
        for (int k16 = 0; k16 < 2; k16++) {
            const uint32_t kbq = qofs + k16 * 32;
            const uint32_t kbk = sofs + k16 * 32;
            uint32_t qh[2][4], ql[2][4], kh[4][4], kl[4][4];
            #pragma unroll
            for (int mt = 0; mt < 2; mt++) {
                ldsm4(qh[mt], aQ[mt] + kbq);
                ldsm4(ql[mt], aQ[mt] + 128 * QROW + kbq);
            }
            #pragma unroll
            for (int np = 0; np < 4; np++) {
                ldsm4(kh[np], aK[np] + kbk);
                ldsm4(kl[np], aK[np] + 128 * KROW + kbk);
            }
            #pragma unroll
            for (int mt = 0; mt < 2; mt++)
                #pragma unroll
                for (int nt = 0; nt < 8; nt++)
                    mma_bf16(acc[mt][nt], qh[mt], &kh[nt >> 1][(nt & 1) * 2]);
            #pragma unroll
            for (int mt = 0; mt < 2; mt++)
                #pragma unroll
                for (int nt = 0; nt < 8; nt++)
                    mma_bf16(acc[mt][nt], qh[mt], &kl[nt >> 1][(nt & 1) * 2]);
            #pragma unroll
            for (int mt = 0; mt < 2; mt++)
                #pragma unroll
                for (int nt = 0; nt < 8; nt++)
                    mma_bf16(acc[mt][nt], ql[mt], &kh[nt >> 1][(nt & 1) * 2]);
        }

        if ((ci & 7) == 7) {
            // ---- per-mtile epilogue (staging for ci+1, ci+2 continues) ----
            const int mtile = mg * 4 + (ci >> 3);
            float rs[4] = {0.f, 0.f, 0.f, 0.f};
            #pragma unroll
            for (int mt = 0; mt < 2; mt++)
                #pragma unroll
                for (int nt = 0; nt < 8; nt++) {
                    float e0 = __expf(acc[mt][nt][0] - MBOUND);
                    float e1 = __expf(acc[mt][nt][1] - MBOUND);
                    float e2 = __expf(acc[mt][nt][2] - MBOUND);
                    float e3 = __expf(acc[mt][nt][3] - MBOUND);
                    rs[mt * 2 + 0] += e0 + e1;
                    rs[mt * 2 + 1] += e2 + e3;

                    uint32_t u0 = __float_as_uint(e0), u1 = __float_as_uint(e1);
                    uint32_t u2 = __float_as_uint(e2), u3 = __float_as_uint(e3);
                    float l0 = e0 - __uint_as_float(u0 & 0xffff0000u);
                    float l1 = e1 - __uint_as_float(u1 & 0xffff0000u);
                    float l2 = e2 - __uint_as_float(u2 & 0xffff0000u);
                    float l3 = e3 - __uint_as_float(u3 & 0xffff0000u);
                    uint32_t ph01 = __byte_perm(u0, u1, 0x7632);
                    uint32_t ph23 = __byte_perm(u2, u3, 0x7632);
                    uint32_t pl01 = __byte_perm(__float_as_uint(l0),
                                                __float_as_uint(l1), 0x7632);
                    uint32_t pl23 = __byte_perm(__float_as_uint(l2),
                                                __float_as_uint(l3), 0x7632);

                    const int nrow = ntile * 128 + m0 + mt * 16 + er;
                    const int mcol = mtile * 128 + n0w + nt * 8 + ec;
                    const size_t o0 = ((size_t)b * NDIM + nrow) * NDIM + mcol;
                    const size_t o1 = ((size_t)b * NDIM + nrow + 8) * NDIM + mcol;
                    *(uint32_t*)&g_Ph[o0] = ph01;
                    *(uint32_t*)&g_Pl[o0] = pl01;
                    *(uint32_t*)&g_Ph[o1] = ph23;
                    *(uint32_t*)&g_Pl[o1] = pl23;
                    acc[mt][nt][0] = 0.f; acc[mt][nt][1] = 0.f;
                    acc[mt][nt][2] = 0.f; acc[mt][nt][3] = 0.f;
                }

            #pragma unroll
            for (int r = 0; r < 4; r++) {
                rs[r] += __shfl_xor_sync(0xffffffffu, rs[r], 1);
                rs[r] += __shfl_xor_sync(0xffffffffu, rs[r], 2);
            }
            if ((lane & 3) == 0) {
                #pragma unroll
                for (int r = 0; r < 4; r++) {
                    const int row = m0 + (r >> 1) * 16 + (r & 1) * 8 + er;
                    part[row * 2 + (wid >> 2)] = rs[r];
                }
            }
            __syncthreads();
            if (tid < 128) {
                const float s = part[tid * 2] + part[tid * 2 + 1];
                g_part[((size_t)b * NDIM + ntile * 128 + tid) * 32 + mtile] = s;
            }
            __syncthreads();
        }
    }
    #undef ISSUE_K
}

// ===========================================================================
// PV mainloop (R14 v5, measured 339 us): 128x128 tile, 2-stage double buffer,
// 8 warps 4x2, warp 32x64, term-major MMA order.
// ===========================================================================
#define SROW      80
#define BUF_BYTES (512 * SROW)          // 40960
#define GEMM_SMEM (2 * BUF_BYTES)       // 81920

__device__ __forceinline__ void gemm_mainloop(
    const __nv_bfloat16* __restrict__ Ah, const __nv_bfloat16* __restrict__ Al,
    const __nv_bfloat16* __restrict__ Bh, const __nv_bfloat16* __restrict__ Bl,
    int kstride, int nchunks, float acc[2][8][4])
{
    extern __shared__ __align__(16) char smem[];
    const uint32_t sb = smem_u32(smem);
    const int tid  = threadIdx.x;
    const int lane = tid & 31;
    const int wid  = tid >> 5;
    const int m0   = (wid & 3) * 32;
    const int n0w  = (wid >> 2) * 64;

    const __nv_bfloat16* src[8];
    uint32_t dof[8];
    #pragma unroll
    for (int i = 0; i < 8; i++) {
        int u = i * 256 + tid;
        int row = u >> 2, c16 = u & 3;
        const __nv_bfloat16* base;
        int r;
        if (row < 128)      { base = Ah; r = row; }
        else if (row < 256) { base = Al; r = row - 128; }
        else if (row < 384) { base = Bh; r = row - 256; }
        else                { base = Bl; r = row - 384; }
        src[i] = base + (size_t)r * kstride + c16 * 8;
        dof[i] = sb + (uint32_t)row * SROW + c16 * 16;
    }

    const int g = lane >> 3, r8 = lane & 7;
    const int rowA = (g & 1) * 8 + r8, kkA = (g >> 1) * 8;
    const int rowB = (g >> 1) * 8 + r8, kkB = (g & 1) * 8;
    uint32_t aAh[2], aAl[2], aBh[4], aBl[4];
    #pragma unroll
    for (int mt = 0; mt < 2; mt++) {
        aAh[mt] = sb + (uint32_t)(0   + m0 + mt * 16 + rowA) * SROW + kkA * 2;
        aAl[mt] = sb + (uint32_t)(128 + m0 + mt * 16 + rowA) * SROW + kkA * 2;
    }
    #pragma unroll
    for (int np = 0; np < 4; np++) {
        aBh[np] = sb + (uint32_t)(256 + n0w + np * 16 + rowB) * SROW + kkB * 2;
        aBl[np] = sb + (uint32_t)(384 + n0w + np * 16 + rowB) * SROW + kkB * 2;
    }

    #pragma unroll
    for (int mt = 0; mt < 2; mt++)
        #pragma unroll
        for (int nt = 0; nt < 8; nt++)
            #pragma unroll
            for (int e = 0; e < 4; e++) acc[mt][nt][e] = 0.f;

    #pragma unroll
    for (int i = 0; i < 8; i++) cp16(dof[i], src[i]);
    CP_COMMIT();

    for (int ci = 0; ci < nchunks; ci++) {
        const uint32_t bofs = (ci & 1) ? BUF_BYTES : 0;
        if (ci + 1 < nchunks) {
            const uint32_t nofs = (ci & 1) ? 0 : BUF_BYTES;
            const int co = (ci + 1) * 32;
            #pragma unroll
            for (int i = 0; i < 8; i++) cp16(dof[i] + nofs, src[i] + co);
            CP_COMMIT();
            CP_WAIT1();
        } else {
            CP_WAIT0();
        }
        __syncthreads();

        #pragma unroll
        for (int k16 = 0; k16 < 2; k16++) {
            const uint32_t kb = bofs + k16 * 32;
            uint32_t ah[2][4], al[2][4], bh[4][4], bl[4][4];
            #pragma unroll
            for (int mt = 0; mt < 2; mt++) {
                ldsm4(ah[mt], aAh[mt] + kb);
                ldsm4(al[mt], aAl[mt] + kb);
            }
            #pragma unroll
            for (int np = 0; np < 4; np++) {
                ldsm4(bh[np], aBh[np] + kb);
                ldsm4(bl[np], aBl[np] + kb);
            }
            #pragma unroll
            for (int mt = 0; mt < 2; mt++)
                #pragma unroll
                for (int nt = 0; nt < 8; nt++)
                    mma_bf16(acc[mt][nt], ah[mt], &bh[nt >> 1][(nt & 1) * 2]);
            #pragma unroll
            for (int mt = 0; mt < 2; mt++)
                #pragma unroll
                for (int nt = 0; nt < 8; nt++)
                    mma_bf16(acc[mt][nt], ah[mt], &bl[nt >> 1][(nt & 1) * 2]);
            #pragma unroll
            for (int mt = 0; mt < 2; mt++)
                #pragma unroll
                for (int nt = 0; nt < 8; nt++)
                    mma_bf16(acc[mt][nt], al[mt], &bh[nt >> 1][(nt & 1) * 2]);
        }
        __syncthreads();
    }
}

// PV: out[b,c,n] = linv[n] * sum_m V[c,m] * P[n,m]
__global__ __launch_bounds__(256, 1) void pv_kernel(float* __restrict__ out)
{
    const int ntile = blockIdx.x;
    const int ct    = blockIdx.y;
    const int b     = blockIdx.z;
    const size_t ao = ((size_t)b * CDIM + (size_t)ct * 128) * NDIM;
    const size_t bo = ((size_t)b * NDIM + (size_t)ntile * 128) * NDIM;

    float acc[2][8][4];
    gemm_mainloop(g_Vh + ao, g_Vl + ao, g_Ph + bo, g_Pl + bo,
                  NDIM, NDIM / 32, acc);

    const int tid = threadIdx.x, lane = tid & 31, wid = tid >> 5;
    const int m0 = (wid & 3) * 32, n0w = (wid >> 2) * 64;
    const int er = lane >> 2, ec = (lane & 3) * 2;

    #pragma unroll
    for (int nt = 0; nt < 8; nt++) {
        const int cc = ntile * 128 + n0w + nt * 8 + ec;
        const float i0 = g_linv[(size_t)b * NDIM + cc];
        const float i1 = g_linv[(size_t)b * NDIM + cc + 1];
        #pragma unroll
        for (int mt = 0; mt < 2; mt++) {
            const int rr = ct * 128 + m0 + mt * 16 + er;
            *(float2*)&out[((size_t)b * CDIM + rr) * NDIM + cc] =
                make_float2(acc[mt][nt][0] * i0, acc[mt][nt][1] * i1);
            *(float2*)&out[((size_t)b * CDIM + rr + 8) * NDIM + cc] =
                make_float2(acc[mt][nt][2] * i0, acc[mt][nt][3] * i1);
        }
    }
}

// ---------------------------------------------------------------------------
// Row-sum reduce: linv[b][n] = 1 / sum_mtile part[b][n][mtile]
// ---------------------------------------------------------------------------
__global__ __launch_bounds__(256) void reduce_kernel()
{
    const int idx = blockIdx.x * 256 + threadIdx.x;
    const float4* p = (const float4*)&g_part[(size_t)idx * 32];
    float s = 0.f;
    #pragma unroll
    for (int i = 0; i < 8; i++) {
        float4 v = p[i];
        s += (v.x + v.y) + (v.z + v.w);
    }
    g_linv[idx] = 1.f / s;
}

// ---------------------------------------------------------------------------
// Projection: out = W(256x256) @ X(256x4096) + bias; emits bf16 hi/lo splits.
// ---------------------------------------------------------------------------
union BF4 { __nv_bfloat16 h[4]; uint2 u; };

__global__ __launch_bounds__(256) void proj_kernel(
    const float* __restrict__ x,
    const float* __restrict__ Wq, const float* __restrict__ bq,
    const float* __restrict__ Wk, const float* __restrict__ bk,
    const float* __restrict__ Wv, const float* __restrict__ bv)
{
    __shared__ float w_s[16][68];
    __shared__ float x_s[16][64];

    const int n0 = blockIdx.x * 64;
    const int o0 = blockIdx.y * 64;
    const int b     = blockIdx.z / 3;
    const int which = blockIdx.z % 3;
    const float* W    = (which == 0) ? Wq : (which == 1) ? Wk : Wv;
    const float* bias = (which == 0) ? bq : (which == 1) ? bk : bv;

    const int t  = threadIdx.x;
    const int tx = t & 15;
    const int ty = t >> 4;

    const float* xb = x + (size_t)b * CDIM * NDIM;

    float acc[4][4];
    #pragma unroll
    for (int i = 0; i < 4; i++)
        #pragma unroll
        for (int j = 0; j < 4; j++) acc[i][j] = 0.f;

    const int lo = t >> 2;
    const int lc = (t & 3) << 2;
    const int xr = t >> 4;
    const int xn = (t & 15) << 2;

    for (int c0 = 0; c0 < CDIM; c0 += 16) {
        float4 wv4 = *(const float4*)&W[(size_t)(o0 + lo) * CDIM + c0 + lc];
        float4 xv4 = *(const float4*)&xb[(size_t)(c0 + xr) * NDIM + n0 + xn];
        __syncthreads();
        w_s[lc + 0][lo] = wv4.x;
        w_s[lc + 1][lo] = wv4.y;
        w_s[lc + 2][lo] = wv4.z;
        w_s[lc + 3][lo] = wv4.w;
        *(float4*)&x_s[xr][xn] = xv4;
        __syncthreads();
        #pragma unroll
        for (int kk = 0; kk < 16; kk++) {
            float4 a4 = *(const float4*)&w_s[kk][ty << 2];
            float4 b4 = *(const float4*)&x_s[kk][tx << 2];
            float a[4] = {a4.x, a4.y, a4.z, a4.w};
            float bb[4] = {b4.x, b4.y, b4.z, b4.w};
            #pragma unroll
            for (int i = 0; i < 4; i++)
                #pragma unroll
                for (int j = 0; j < 4; j++)
                    acc[i][j] = fmaf(a[i], bb[j], acc[i][j]);
        }
    }

    float bo[4];
    #pragma unroll
    for (int i = 0; i < 4; i++) bo[i] = bias[o0 + (ty << 2) + i];

    if (which != 2) {
        __nv_bfloat16* dh = (which == 0) ? g_Qh : g_Kh;
        __nv_bfloat16* dl = (which == 0) ? g_Ql : g_Kl;
        #pragma unroll
        for (int j = 0; j < 4; j++) {
            const int n = n0 + (tx << 2) + j;
            BF4 H, L;
            #pragma unroll
            for (int i = 0; i < 4; i++) {
                float v = acc[i][j] + bo[i];
                H.h[i] = __float2bfloat16(v);
                L.h[i] = __float2bfloat16(v - __bfloat162float(H.h[i]));
            }
            const size_t base = ((size_t)b * NDIM + n) * CDIM + o0 + (ty << 2);
            *(uint2*)&dh[base] = H.u;
            *(uint2*)&dl[base] = L.u;
        }
    } else {
        #pragma unroll
        for (int i = 0; i < 4; i++) {
            const int o = o0 + (ty << 2) + i;
            BF4 H, L;
            #pragma unroll
            for (int j = 0; j < 4; j++) {
                float v = acc[i][j] + bo[i];
                H.h[j] = __float2bfloat16(v);
                L.h[j] = __float2bfloat16(v - __bfloat162float(H.h[j]));
            }
            const size_t base = ((size_t)b * CDIM + o) * NDIM + n0 + (tx << 2);
            *(uint2*)&g_Vh[base] = H.u;
            *(uint2*)&g_Vl[base] = L.u;
        }
    }
}

// ---------------------------------------------------------------------------
extern "C" void kernel_launch(void* const* d_in, const int* in_sizes, int n_in,
                              void* d_out, int out_size)
{
    const float* x  = (const float*)d_in[0];
    const float* Wq = (const float*)d_in[1];
    const float* bq = (const float*)d_in[2];
    const float* Wk = (const float*)d_in[3];
    const float* bk = (const float*)d_in[4];
    const float* Wv = (const float*)d_in[5];
    const float* bv = (const float*)d_in[6];
    float* out = (float*)d_out;

    cudaFuncSetAttribute(qk_kernel,
                         cudaFuncAttributeMaxDynamicSharedMemorySize, QK_SMEM);
    cudaFuncSetAttribute(pv_kernel,
                         cudaFuncAttributeMaxDynamicSharedMemorySize, GEMM_SMEM);

    dim3 pg(NDIM / 64, CDIM / 64, BDIM * 3);
    proj_kernel<<<pg, 256>>>(x, Wq, bq, Wk, bk, Wv, bv);

    dim3 qg(8, NDIM / 128, BDIM);                // (mgroup, ntile, B) = 1024 CTAs
    qk_kernel<<<qg, 256, QK_SMEM>>>();

    reduce_kernel<<<(BDIM * NDIM) / 256, 256>>>();

    dim3 vg(NDIM / 128, CDIM / 128, BDIM);       // (ntile, ctile, B)
    pv_kernel<<<vg, 256, GEMM_SMEM>>>(out);
}